// round 12
// baseline (speedup 1.0000x reference)
#include <cuda_runtime.h>
#include <cuda_fp16.h>
#include <math.h>
#include <math_constants.h>

#define B_  2
#define T_  2048
#define C_  1024
#define H_  16
#define D_  64
#define KCH 128              // GEMM K elems per pipeline chunk
#define NCH (C_ / KCH)       // 8 chunks

#define LOG2E 1.44269504f

typedef unsigned int u32;

// ---------------------------------------------------------------------------
// Scratch (__device__ globals: allocation-free rule)
// ---------------------------------------------------------------------------
static __device__ __align__(16) float g_bias[H_*T_];
static __device__ __align__(16) float g_cos[T_*D_];
static __device__ __align__(16) float g_sin[T_*D_];
// fp16 operands
static __device__ __align__(16) __half g_xf[(size_t)B_*T_*C_];      // x fp16
static __device__ __align__(16) __half g_yf[(size_t)B_*T_*C_];      // attn out fp16
static __device__ __align__(16) __half g_w[4 * (size_t)C_*C_];      // weights fp16
// attention operands (head layout [B,H,T,D]), written by fused qkv epilogue
static __device__ __align__(16) __half g_qf[(size_t)B_*H_*T_*D_];   // pre-scaled by 0.125*log2e
static __device__ __align__(16) __half g_kf[(size_t)B_*H_*T_*D_];
static __device__ __align__(16) __half g_vf[(size_t)B_*H_*T_*D_];

// ---------------------------------------------------------------------------
// Baseline-PTX helpers (sm_80-compatible: ldmatrix / mma.sync / cp.async)
// ---------------------------------------------------------------------------
__device__ __forceinline__ u32 smem_u32(const void* p) {
    u32 a;
    asm("{ .reg .u64 t; cvta.to.shared.u64 t, %1; cvt.u32.u64 %0, t; }" : "=r"(a) : "l"(p));
    return a;
}
__device__ __forceinline__ void ldsm_x4(u32 addr, u32& r0, u32& r1, u32& r2, u32& r3) {
    asm volatile("ldmatrix.sync.aligned.m8n8.x4.shared.b16 {%0,%1,%2,%3}, [%4];"
                 : "=r"(r0), "=r"(r1), "=r"(r2), "=r"(r3) : "r"(addr));
}
__device__ __forceinline__ void ldsm_x4_t(u32 addr, u32& r0, u32& r1, u32& r2, u32& r3) {
    asm volatile("ldmatrix.sync.aligned.m8n8.x4.trans.shared.b16 {%0,%1,%2,%3}, [%4];"
                 : "=r"(r0), "=r"(r1), "=r"(r2), "=r"(r3) : "r"(addr));
}
__device__ __forceinline__ void mma_f16(float* c, u32 a0, u32 a1, u32 a2, u32 a3,
                                        u32 b0, u32 b1) {
    asm volatile("mma.sync.aligned.m16n8k16.row.col.f32.f16.f16.f32 "
                 "{%0,%1,%2,%3}, {%4,%5,%6,%7}, {%8,%9}, {%0,%1,%2,%3};"
                 : "+f"(c[0]), "+f"(c[1]), "+f"(c[2]), "+f"(c[3])
                 : "r"(a0), "r"(a1), "r"(a2), "r"(a3), "r"(b0), "r"(b1));
}
#define CP_ASYNC16(dst, src) \
    asm volatile("cp.async.cg.shared.global [%0], [%1], 16;" :: "r"(dst), "l"(src))
#define CP_COMMIT() asm volatile("cp.async.commit_group;" ::: "memory")
#define CP_WAIT2()  asm volatile("cp.async.wait_group 2;" ::: "memory")
#define CP_WAIT1()  asm volatile("cp.async.wait_group 1;" ::: "memory")
#define CP_WAIT0()  asm volatile("cp.async.wait_group 0;" ::: "memory")

// packed fp16x2 2^x (one MUFU for two values)
__device__ __forceinline__ u32 ex2_f16x2(float a, float b) {
    __half2 h = __floats2half2_rn(a, b);
    u32 r;
    asm("ex2.approx.f16x2 %0, %1;" : "=r"(r) : "r"(*(u32*)&h));
    return r;
}
__device__ __forceinline__ float ex2_f32(float a) {
    float r;
    asm("ex2.approx.f32 %0, %1;" : "=f"(r) : "f"(a));
    return r;
}

// ---------------------------------------------------------------------------
// Fused prep: convert x, convert W, build tables (one launch)
// ---------------------------------------------------------------------------
__global__ void prep_kernel(const float* __restrict__ xin,
                            const float* __restrict__ Wq, const float* __restrict__ Wk,
                            const float* __restrict__ Wv, const float* __restrict__ Wp,
                            const float* __restrict__ rel_table) {
    int bx = blockIdx.x;
    int tid = threadIdx.x;
    if (bx < 4096) {
        int i = bx * 256 + tid;
        float4 v = ((const float4*)xin)[i];
        ((__half2*)g_xf)[i * 2 + 0] = __floats2half2_rn(v.x, v.y);
        ((__half2*)g_xf)[i * 2 + 1] = __floats2half2_rn(v.z, v.w);
    } else if (bx < 8192) {
        int bx2 = bx - 4096;
        int z = bx2 >> 10;
        const float* W = z == 0 ? Wq : z == 1 ? Wk : z == 2 ? Wv : Wp;
        __half* ow = g_w + (size_t)z * C_ * C_;
        int i = (bx2 & 1023) * 256 + tid;
        float4 v = ((const float4*)W)[i];
        ((__half2*)ow)[i * 2 + 0] = __floats2half2_rn(v.x, v.y);
        ((__half2*)ow)[i * 2 + 1] = __floats2half2_rn(v.z, v.w);
    } else {
        int idx = (bx - 8192) * 256 + tid;
        if (idx < T_ * D_) {
            int t = idx >> 6;
            int d = idx & 63;
            int j = d & 31;
            float inv = (float)pow(10000.0, -(double)(2 * j) / 64.0);
            float fr = (float)t * inv;
            g_cos[idx] = cosf(fr);
            g_sin[idx] = sinf(fr);
        }
        if (idx < H_ * T_) {
            int h = idx / T_;
            int n = idx % T_;
            int bucket;
            if (n < 16) {
                bucket = n;
            } else {
                float v = logf((float)n * (1.0f / 16.0f)) / 2.0794415416798357f * 16.0f;
                bucket = 16 + (int)v;
                if (bucket > 31) bucket = 31;
            }
            g_bias[idx] = rel_table[bucket * H_ + h];
        }
    }
}

// ---------------------------------------------------------------------------
// HMMA GEMM v7: KCH=128, 3-stage pipeline, 8 chunks, 1 sync/chunk.
// 128x128 CTA, 512 threads (16 warps 4x4, warp tile 32x32).
// mode 0: proj (fp32 out)  1: Q (rope+scale)  2: K (rope)  3: V (fp16 direct)
// ---------------------------------------------------------------------------
#define SA 136       // A smem row stride (halves): 128 + 8 pad
#define SB 136       // B smem row stride (halves)
#define A_OFF 0
#define B_OFF (128 * SA * 2)                      // 34816
#define STAGE_BYTES (B_OFF + KCH * SB * 2)        // 69632
#define SMEM_TOTAL (3 * STAGE_BYTES)              // 208896

__device__ __forceinline__ void hmma_gemm_body(
        const __half* __restrict__ Af, const __half* __restrict__ Wf,
        const float* __restrict__ bias, void* outp, int mode) {
    extern __shared__ char smem[];
    u32 sb = smem_u32(smem);

    int tid = threadIdx.x;
    int lane = tid & 31;
    int wid = tid >> 5;
    int wm = wid & 3;
    int wn = wid >> 2;
    int bm = blockIdx.y * 128;
    int bn = blockIdx.x * 128;

    float acc[2][4][4];
#pragma unroll
    for (int i = 0; i < 2; i++)
#pragma unroll
        for (int j = 0; j < 4; j++)
#pragma unroll
            for (int r = 0; r < 4; r++) acc[i][j][r] = 0.f;

    auto load_chunk = [&](int c) {
        u32 st = sb + (c % 3) * STAGE_BYTES;
        int c0 = c * KCH;
        // A: 128 rows x 128 halves = 2048 16B segs
#pragma unroll
        for (int u = tid; u < 2048; u += 512) {
            int row = u >> 4, seg = u & 15;
            size_t gofs = (size_t)(bm + row) * C_ + c0 + seg * 8;
            CP_ASYNC16(st + A_OFF + (u32)(row * SA + seg * 8) * 2, Af + gofs);
        }
        // B: 128 k-rows x 128 halves
#pragma unroll
        for (int u = tid; u < 2048; u += 512) {
            int row = u >> 4, seg = u & 15;
            size_t gofs = (size_t)(c0 + row) * C_ + bn + seg * 8;
            CP_ASYNC16(st + B_OFF + (u32)(row * SB + seg * 8) * 2, Wf + gofs);
        }
        CP_COMMIT();
    };

    load_chunk(0);
    if (NCH > 1) load_chunk(1);

    int lr = lane & 15;
    int lh = lane >> 4;

    for (int c = 0; c < NCH; c++) {
        if (c < NCH - 1) CP_WAIT1();
        else             CP_WAIT0();
        __syncthreads();
        if (c + 2 < NCH) load_chunk(c + 2);   // after sync: stage (c+2)%3 free

        u32 st = sb + (c % 3) * STAGE_BYTES;
#pragma unroll
        for (int ks = 0; ks < 8; ks++) {
            int k0 = ks * 16;
            u32 af[2][4];
#pragma unroll
            for (int mt = 0; mt < 2; mt++) {
                u32 arow = (u32)(wm * 32 + mt * 16 + lr);
                u32 aoff = (arow * SA + k0 + lh * 8) * 2;
                ldsm_x4(st + A_OFF + aoff, af[mt][0], af[mt][1], af[mt][2], af[mt][3]);
            }
#pragma unroll
            for (int np = 0; np < 2; np++) {
                u32 brow = (u32)(k0 + lr);
                u32 bcol = (u32)(wn * 32 + np * 16 + lh * 8);
                u32 boff = (brow * SB + bcol) * 2;
                u32 b0, b1, b2, b3;
                ldsm_x4_t(st + B_OFF + boff, b0, b1, b2, b3);
#pragma unroll
                for (int mt = 0; mt < 2; mt++) {
                    mma_f16(acc[mt][np * 2],     af[mt][0], af[mt][1], af[mt][2], af[mt][3], b0, b1);
                    mma_f16(acc[mt][np * 2 + 1], af[mt][0], af[mt][1], af[mt][2], af[mt][3], b2, b3);
                }
            }
        }
    }
    __syncthreads();

    int rq = lane >> 2;
    int cq = (lane & 3) * 2;

    if (mode == 0) {
        float* out = (float*)outp;
#pragma unroll
        for (int mt = 0; mt < 2; mt++)
#pragma unroll
            for (int nt = 0; nt < 4; nt++) {
                int gc = bn + wn * 32 + nt * 8 + cq;
                float b0 = bias[gc], b1 = bias[gc + 1];
#pragma unroll
                for (int half = 0; half < 2; half++) {
                    int grow = bm + wm * 32 + mt * 16 + rq + half * 8;
                    float2 o;
                    o.x = acc[mt][nt][half * 2 + 0] + b0;
                    o.y = acc[mt][nt][half * 2 + 1] + b1;
                    *(float2*)(out + (size_t)grow * C_ + gc) = o;
                }
            }
    } else if (mode == 3) {
        __half* out = (__half*)outp;
#pragma unroll
        for (int mt = 0; mt < 2; mt++)
#pragma unroll
            for (int nt = 0; nt < 4; nt++) {
                int gc = bn + wn * 32 + nt * 8 + cq;
                float b0 = bias[gc], b1 = bias[gc + 1];
                int h = gc >> 6, d0 = gc & 63;
#pragma unroll
                for (int half = 0; half < 2; half++) {
                    int grow = bm + wm * 32 + mt * 16 + rq + half * 8;
                    int b = grow >> 11, t = grow & (T_ - 1);
                    __half2 o = __floats2half2_rn(acc[mt][nt][half * 2 + 0] + b0,
                                                  acc[mt][nt][half * 2 + 1] + b1);
                    *(__half2*)(out + (((size_t)b * H_ + h) * T_ + t) * D_ + d0) = o;
                }
            }
    } else {
        // Q/K: stage fp32 tile in smem, rope pairs (d, d+32) -> fp16, x2 vectorized
        float* cs = (float*)smem;
#pragma unroll
        for (int mt = 0; mt < 2; mt++)
#pragma unroll
            for (int nt = 0; nt < 4; nt++) {
                int lc = wn * 32 + nt * 8 + cq;
                int gc = bn + lc;
                float b0 = bias[gc], b1 = bias[gc + 1];
#pragma unroll
                for (int half = 0; half < 2; half++) {
                    int lrow = wm * 32 + mt * 16 + rq + half * 8;
                    cs[lrow * 132 + lc]     = acc[mt][nt][half * 2 + 0] + b0;
                    cs[lrow * 132 + lc + 1] = acc[mt][nt][half * 2 + 1] + b1;
                }
            }
        __syncthreads();

        __half* out = (__half*)outp;
        // Q carries the full softmax scale in log2 domain: 1/8 * log2(e)
        float qscale = (mode == 1) ? 0.125f * LOG2E : 1.0f;
#pragma unroll
        for (int u = tid; u < 4096; u += 512) {
            int r  = u >> 5;                 // row 0..127
            int pp = u & 31;
            int hh = pp >> 4;                // which 64-col head half
            int dd = (pp & 15) * 2;          // 0..30 even
            int c  = hh * 64 + dd;
            int gc = bn + c;
            int h = gc >> 6;
            int grow = bm + r;
            int b = grow >> 11, t = grow & (T_ - 1);
            float x1a = cs[r * 132 + c],      x1b = cs[r * 132 + c + 1];
            float x2a = cs[r * 132 + c + 32], x2b = cs[r * 132 + c + 33];
            float2 cv = *(const float2*)&g_cos[(t << 6) + dd];
            float2 sv = *(const float2*)&g_sin[(t << 6) + dd];
            __half2 ya = __floats2half2_rn((x1a * cv.x - x2a * sv.x) * qscale,
                                           (x1b * cv.y - x2b * sv.y) * qscale);
            __half2 yb = __floats2half2_rn((x2a * cv.x + x1a * sv.x) * qscale,
                                           (x2b * cv.y + x1b * sv.y) * qscale);
            __half* dp = out + (((size_t)b * H_ + h) * T_ + t) * D_ + dd;
            *(__half2*)dp        = ya;
            *(__half2*)(dp + 32) = yb;
        }
    }
}

__global__ __launch_bounds__(512, 1) void mma_qkv_kernel(
        const float* __restrict__ bq, const float* __restrict__ bk,
        const float* __restrict__ bv) {
    int z = blockIdx.z;
    const __half* Wf = g_w + (size_t)z * C_ * C_;
    const float* bias = z == 0 ? bq : z == 1 ? bk : bv;
    void* dst = z == 0 ? (void*)g_qf : z == 1 ? (void*)g_kf : (void*)g_vf;
    hmma_gemm_body(g_xf, Wf, bias, dst, z + 1);
}

__global__ __launch_bounds__(512, 1) void mma_proj_kernel(
        const float* __restrict__ bp, float* __restrict__ out) {
    hmma_gemm_body(g_yf, g_w + 3 * (size_t)C_ * C_, bp, out, 0);
}

// ---------------------------------------------------------------------------
// HMMA flash attention v6: 64 q / CTA (4 warps), 4-stage KV pipeline,
// log2-domain softmax with ex2.approx.f16x2, causal fragment skipping.
// ---------------------------------------------------------------------------
#define AST 72
#define KV_ARRB (64 * AST * 2)               // 9216
#define KV_STAGEB (2 * KV_ARRB)              // 18432 (K, V)
#define AT_SMEM (4 * KV_STAGEB + T_ * 4)     // 81920

__global__ __launch_bounds__(128) void attn_mma_kernel() {
    extern __shared__ char asm_[];
    u32 sbase = smem_u32(asm_);
    float* sbias = (float*)(asm_ + 4 * KV_STAGEB);
    __half* sst = (__half*)asm_;

    int bh = blockIdx.y;
    int h = bh & (H_ - 1);
    int qb = gridDim.x - 1 - blockIdx.x;      // big-work CTAs first
    int q0 = qb * 64;
    int tid = threadIdx.x;
    int lane = tid & 31;
    int w = tid >> 5;                         // 0..3
    int qw = q0 + w * 16;

    const __half* qf = g_qf + ((size_t)bh * T_ + q0) * D_;
    size_t kvo = (size_t)bh * T_ * D_;

    {
        const float4* b4 = (const float4*)(g_bias + h * T_);
        const float bs = 0.125f * LOG2E;
        for (int i = tid; i < T_ / 4; i += 128) {
            float4 v = b4[i];
            v.x *= bs; v.y *= bs; v.z *= bs; v.w *= bs;
            ((float4*)sbias)[i] = v;
        }
    }
    // stage Q (64x64 fp16) into stage-0 area
    for (int u = tid; u < 512; u += 128) {
        int row = u >> 3, seg = u & 7;
        *(uint4*)(sst + row * AST + seg * 8) =
            *(const uint4*)(qf + row * 64 + seg * 8);
    }
    __syncthreads();

    u32 qfr[4][4];
    {
        int lr = lane & 15, lh = lane >> 4;
#pragma unroll
        for (int kc = 0; kc < 4; kc++) {
            u32 off = (u32)((w * 16 + lr) * AST + kc * 16 + lh * 8) * 2;
            ldsm_x4(sbase + off, qfr[kc][0], qfr[kc][1], qfr[kc][2], qfr[kc][3]);
        }
    }
    __syncthreads();

    auto load_kv = [&](int blk, int s) {
        u32 st = sbase + s * KV_STAGEB;
        const __half* kf = g_kf + kvo + (size_t)blk * 64 * 64;
        const __half* vf = g_vf + kvo + (size_t)blk * 64 * 64;
#pragma unroll
        for (int u = tid; u < 512; u += 128) {
            int row = u >> 3, seg = u & 7;
            u32 doff = (u32)(row * AST + seg * 8) * 2;
            int goff = row * 64 + seg * 8;
            CP_ASYNC16(st + doff,           kf + goff);
            CP_ASYNC16(st + KV_ARRB + doff, vf + goff);
        }
        CP_COMMIT();
    };

    int nblk = qb + 1;
    load_kv(0, 0);
    if (nblk > 1) load_kv(1, 1);

    float mlo = -CUDART_INF_F, mhi = -CUDART_INF_F;
    float llo = 0.f, lhi = 0.f;
    float oacc[8][4];
#pragma unroll
    for (int i = 0; i < 8; i++)
#pragma unroll
        for (int j = 0; j < 4; j++) oacc[i][j] = 0.f;

    int rlo = qw + (lane >> 2);
    int rhi = rlo + 8;
    int cq = (lane & 3) * 2;

    for (int blk = 0; blk < nblk; blk++) {
        if (blk + 2 < nblk) load_kv(blk + 2, (blk + 2) & 3);
        if (blk < nblk - 2)      CP_WAIT2();
        else if (blk < nblk - 1) CP_WAIT1();
        else                     CP_WAIT0();
        __syncthreads();

        int j0 = blk * 64;
        {
            u32 st = sbase + (blk & 3) * KV_STAGEB;
            int lr = lane & 15, lh = lane >> 4;

            // S = Q K^T (log2 domain; skip fully-masked 16-key fragments)
            float sacc[8][4];
#pragma unroll
            for (int i = 0; i < 8; i++)
#pragma unroll
                for (int j = 0; j < 4; j++) sacc[i][j] = 0.f;
#pragma unroll
            for (int kg = 0; kg < 4; kg++) {
                if (j0 + kg * 16 <= qw + 15) {
#pragma unroll
                    for (int kc = 0; kc < 4; kc++) {
                        u32 off = (u32)((kg * 16 + lr) * AST + kc * 16 + lh * 8) * 2;
                        u32 k0, k1, k2, k3;
                        ldsm_x4(st + off, k0, k1, k2, k3);
                        mma_f16(sacc[2 * kg],     qfr[kc][0], qfr[kc][1], qfr[kc][2], qfr[kc][3], k0, k2);
                        mma_f16(sacc[2 * kg + 1], qfr[kc][0], qfr[kc][1], qfr[kc][2], qfr[kc][3], k1, k3);
                    }
                }
            }

            // bias + causal mask
#pragma unroll
            for (int nf = 0; nf < 8; nf++) {
                int jc = j0 + nf * 8 + cq;
                int d0 = rlo - jc;
                int d2 = rhi - jc;
                sacc[nf][0] = (d0 >= 0) ? sacc[nf][0] + sbias[d0]     : -CUDART_INF_F;
                sacc[nf][1] = (d0 >= 1) ? sacc[nf][1] + sbias[d0 - 1] : -CUDART_INF_F;
                sacc[nf][2] = (d2 >= 0) ? sacc[nf][2] + sbias[d2]     : -CUDART_INF_F;
                sacc[nf][3] = (d2 >= 1) ? sacc[nf][3] + sbias[d2 - 1] : -CUDART_INF_F;
            }

            // row max
            float bmlo = sacc[0][0], bmhi = sacc[0][2];
#pragma unroll
            for (int nf = 0; nf < 8; nf++) {
                bmlo = fmaxf(bmlo, fmaxf(sacc[nf][0], sacc[nf][1]));
                bmhi = fmaxf(bmhi, fmaxf(sacc[nf][2], sacc[nf][3]));
            }
            bmlo = fmaxf(bmlo, __shfl_xor_sync(0xffffffffu, bmlo, 1));
            bmlo = fmaxf(bmlo, __shfl_xor_sync(0xffffffffu, bmlo, 2));
            bmhi = fmaxf(bmhi, __shfl_xor_sync(0xffffffffu, bmhi, 1));
            bmhi = fmaxf(bmhi, __shfl_xor_sync(0xffffffffu, bmhi, 2));

            float nmlo = fmaxf(mlo, bmlo), nmhi = fmaxf(mhi, bmhi);
            float clo = ex2_f32(mlo - nmlo), chi = ex2_f32(mhi - nmhi);
            mlo = nmlo; mhi = nmhi;
            llo *= clo; lhi *= chi;
#pragma unroll
            for (int nf = 0; nf < 8; nf++) {
                oacc[nf][0] *= clo; oacc[nf][1] *= clo;
                oacc[nf][2] *= chi; oacc[nf][3] *= chi;
            }

            // P = 2^(s - m) via packed fp16 ex2; l from rounded P
            u32 pf[4][4];
#pragma unroll
            for (int nf = 0; nf < 8; nf++) {
                if (j0 + (nf >> 1) * 16 <= qw + 15) {
                    u32 p01 = ex2_f16x2(sacc[nf][0] - mlo, sacc[nf][1] - mlo);
                    u32 p23 = ex2_f16x2(sacc[nf][2] - mhi, sacc[nf][3] - mhi);
                    float2 f01 = __half22float2(*(__half2*)&p01);
                    float2 f23 = __half22float2(*(__half2*)&p23);
                    llo += f01.x + f01.y;
                    lhi += f23.x + f23.y;
                    int kc = nf >> 1, half = nf & 1;
                    pf[kc][half * 2 + 0] = p01;
                    pf[kc][half * 2 + 1] = p23;
                }
            }

            // O += P V (skip fully-masked 16-key fragments)
#pragma unroll
            for (int dg = 0; dg < 4; dg++) {
#pragma unroll
                for (int kc = 0; kc < 4; kc++) {
                    if (j0 + kc * 16 <= qw + 15) {
                        u32 off = (u32)((kc * 16 + lr) * AST + dg * 16 + lh * 8) * 2;
                        u32 v0, v1, v2, v3;
                        ldsm_x4_t(st + KV_ARRB + off, v0, v1, v2, v3);
                        mma_f16(oacc[2 * dg],     pf[kc][0], pf[kc][1], pf[kc][2], pf[kc][3], v0, v1);
                        mma_f16(oacc[2 * dg + 1], pf[kc][0], pf[kc][1], pf[kc][2], pf[kc][3], v2, v3);
                    }
                }
            }
        }
    }

    llo += __shfl_xor_sync(0xffffffffu, llo, 1);
    llo += __shfl_xor_sync(0xffffffffu, llo, 2);
    lhi += __shfl_xor_sync(0xffffffffu, lhi, 1);
    lhi += __shfl_xor_sync(0xffffffffu, lhi, 2);
    float ilo = 1.f / llo, ihi = 1.f / lhi;

    // write fp16 directly to proj input g_yf [B*T, C]
    int b = bh >> 4;
    __half* ylo = g_yf + ((size_t)b * T_ + rlo) * C_ + h * D_ + cq;
    __half* yhi = g_yf + ((size_t)b * T_ + rhi) * C_ + h * D_ + cq;
#pragma unroll
    for (int nf = 0; nf < 8; nf++) {
        *(__half2*)(ylo + nf * 8) = __floats2half2_rn(oacc[nf][0] * ilo, oacc[nf][1] * ilo);
        *(__half2*)(yhi + nf * 8) = __floats2half2_rn(oacc[nf][2] * ihi, oacc[nf][3] * ihi);
    }
}

// ---------------------------------------------------------------------------
extern "C" void kernel_launch(void* const* d_in, const int* in_sizes, int n_in,
                              void* d_out, int out_size) {
    const float* x   = (const float*)d_in[0];
    const float* Wq  = (const float*)d_in[1];
    const float* bq  = (const float*)d_in[2];
    const float* Wk  = (const float*)d_in[3];
    const float* bk  = (const float*)d_in[4];
    const float* Wv  = (const float*)d_in[5];
    const float* bv  = (const float*)d_in[6];
    const float* Wp  = (const float*)d_in[7];
    const float* bp  = (const float*)d_in[8];
    const float* tbl = (const float*)d_in[9];
    float* out = (float*)d_out;

    cudaFuncSetAttribute(mma_qkv_kernel,
                         cudaFuncAttributeMaxDynamicSharedMemorySize, SMEM_TOTAL);
    cudaFuncSetAttribute(mma_proj_kernel,
                         cudaFuncAttributeMaxDynamicSharedMemorySize, SMEM_TOTAL);
    cudaFuncSetAttribute(attn_mma_kernel,
                         cudaFuncAttributeMaxDynamicSharedMemorySize, AT_SMEM);

    prep_kernel<<<8704, 256>>>(x, Wq, Wk, Wv, Wp, tbl);

    mma_qkv_kernel<<<dim3(C_ / 128, (B_ * T_) / 128, 3), 512, SMEM_TOTAL>>>(bq, bk, bv);

    attn_mma_kernel<<<dim3(T_ / 64, B_ * H_), 128, AT_SMEM>>>();

    mma_proj_kernel<<<dim3(C_ / 128, (B_ * T_) / 128), 512, SMEM_TOTAL>>>(bp, out);
}

// round 13
// speedup vs baseline: 1.1867x; 1.1867x over previous
#include <cuda_runtime.h>
#include <cuda_fp16.h>
#include <math.h>
#include <math_constants.h>

#define B_  2
#define T_  2048
#define C_  1024
#define H_  16
#define D_  64
#define KCH 64               // GEMM K elems per pipeline chunk
#define NCH (C_ / KCH)       // 16 chunks

#define LOG2E 1.44269504f

typedef unsigned int u32;

// ---------------------------------------------------------------------------
// Scratch (__device__ globals: allocation-free rule)
// ---------------------------------------------------------------------------
static __device__ __align__(16) float g_bias[H_*T_];
static __device__ __align__(16) float g_cos[T_*D_];
static __device__ __align__(16) float g_sin[T_*D_];
// fp16 operands
static __device__ __align__(16) __half g_xf[(size_t)B_*T_*C_];      // x fp16
static __device__ __align__(16) __half g_yf[(size_t)B_*T_*C_];      // attn out fp16
static __device__ __align__(16) __half g_w[4 * (size_t)C_*C_];      // weights fp16
// attention operands (head layout [B,H,T,D]), written by fused qkv epilogue
static __device__ __align__(16) __half g_qf[(size_t)B_*H_*T_*D_];   // pre-scaled by 0.125*log2e
static __device__ __align__(16) __half g_kf[(size_t)B_*H_*T_*D_];
static __device__ __align__(16) __half g_vf[(size_t)B_*H_*T_*D_];

// ---------------------------------------------------------------------------
// Baseline-PTX helpers (sm_80-compatible: ldmatrix / mma.sync / cp.async)
// ---------------------------------------------------------------------------
__device__ __forceinline__ u32 smem_u32(const void* p) {
    u32 a;
    asm("{ .reg .u64 t; cvta.to.shared.u64 t, %1; cvt.u32.u64 %0, t; }" : "=r"(a) : "l"(p));
    return a;
}
__device__ __forceinline__ void ldsm_x4(u32 addr, u32& r0, u32& r1, u32& r2, u32& r3) {
    asm volatile("ldmatrix.sync.aligned.m8n8.x4.shared.b16 {%0,%1,%2,%3}, [%4];"
                 : "=r"(r0), "=r"(r1), "=r"(r2), "=r"(r3) : "r"(addr));
}
__device__ __forceinline__ void ldsm_x4_t(u32 addr, u32& r0, u32& r1, u32& r2, u32& r3) {
    asm volatile("ldmatrix.sync.aligned.m8n8.x4.trans.shared.b16 {%0,%1,%2,%3}, [%4];"
                 : "=r"(r0), "=r"(r1), "=r"(r2), "=r"(r3) : "r"(addr));
}
__device__ __forceinline__ void mma_f16(float* c, u32 a0, u32 a1, u32 a2, u32 a3,
                                        u32 b0, u32 b1) {
    asm volatile("mma.sync.aligned.m16n8k16.row.col.f32.f16.f16.f32 "
                 "{%0,%1,%2,%3}, {%4,%5,%6,%7}, {%8,%9}, {%0,%1,%2,%3};"
                 : "+f"(c[0]), "+f"(c[1]), "+f"(c[2]), "+f"(c[3])
                 : "r"(a0), "r"(a1), "r"(a2), "r"(a3), "r"(b0), "r"(b1));
}
#define CP_ASYNC16(dst, src) \
    asm volatile("cp.async.cg.shared.global [%0], [%1], 16;" :: "r"(dst), "l"(src))
#define CP_COMMIT() asm volatile("cp.async.commit_group;" ::: "memory")
#define CP_WAIT2()  asm volatile("cp.async.wait_group 2;" ::: "memory")
#define CP_WAIT1()  asm volatile("cp.async.wait_group 1;" ::: "memory")
#define CP_WAIT0()  asm volatile("cp.async.wait_group 0;" ::: "memory")

// packed fp16x2 2^x (one MUFU for two values)
__device__ __forceinline__ u32 ex2_f16x2(float a, float b) {
    __half2 h = __floats2half2_rn(a, b);
    u32 r;
    asm("ex2.approx.f16x2 %0, %1;" : "=r"(r) : "r"(*(u32*)&h));
    return r;
}
__device__ __forceinline__ float ex2_f32(float a) {
    float r;
    asm("ex2.approx.f32 %0, %1;" : "=f"(r) : "f"(a));
    return r;
}

// ---------------------------------------------------------------------------
// Fused prep: convert x, convert W, build tables (one launch)
// ---------------------------------------------------------------------------
__global__ void prep_kernel(const float* __restrict__ xin,
                            const float* __restrict__ Wq, const float* __restrict__ Wk,
                            const float* __restrict__ Wv, const float* __restrict__ Wp,
                            const float* __restrict__ rel_table) {
    int bx = blockIdx.x;
    int tid = threadIdx.x;
    if (bx < 4096) {
        int i = bx * 256 + tid;
        float4 v = ((const float4*)xin)[i];
        ((__half2*)g_xf)[i * 2 + 0] = __floats2half2_rn(v.x, v.y);
        ((__half2*)g_xf)[i * 2 + 1] = __floats2half2_rn(v.z, v.w);
    } else if (bx < 8192) {
        int bx2 = bx - 4096;
        int z = bx2 >> 10;
        const float* W = z == 0 ? Wq : z == 1 ? Wk : z == 2 ? Wv : Wp;
        __half* ow = g_w + (size_t)z * C_ * C_;
        int i = (bx2 & 1023) * 256 + tid;
        float4 v = ((const float4*)W)[i];
        ((__half2*)ow)[i * 2 + 0] = __floats2half2_rn(v.x, v.y);
        ((__half2*)ow)[i * 2 + 1] = __floats2half2_rn(v.z, v.w);
    } else {
        int idx = (bx - 8192) * 256 + tid;
        if (idx < T_ * D_) {
            int t = idx >> 6;
            int d = idx & 63;
            int j = d & 31;
            float inv = (float)pow(10000.0, -(double)(2 * j) / 64.0);
            float fr = (float)t * inv;
            g_cos[idx] = cosf(fr);
            g_sin[idx] = sinf(fr);
        }
        if (idx < H_ * T_) {
            int h = idx / T_;
            int n = idx % T_;
            int bucket;
            if (n < 16) {
                bucket = n;
            } else {
                float v = logf((float)n * (1.0f / 16.0f)) / 2.0794415416798357f * 16.0f;
                bucket = 16 + (int)v;
                if (bucket > 31) bucket = 31;
            }
            g_bias[idx] = rel_table[bucket * H_ + h];
        }
    }
}

// ---------------------------------------------------------------------------
// HMMA GEMM (R11 config): KCH=64, 4-stage cp.async pipeline, 1 sync/chunk.
// 128x128 CTA, 512 threads (16 warps 4x4, warp tile 32x32).
// mode 0: proj (fp32 out)  1: Q (rope+log2e scale)  2: K (rope)  3: V (fp16)
// ---------------------------------------------------------------------------
#define SA 72        // A smem row stride (halves)
#define SB 136       // B smem row stride (halves)
#define A_OFF 0
#define B_OFF (128 * SA * 2)                      // 18432
#define STAGE_BYTES (B_OFF + KCH * SB * 2)        // 35840
#define SMEM_TOTAL (4 * STAGE_BYTES)              // 143360

__device__ __forceinline__ void hmma_gemm_body(
        const __half* __restrict__ Af, const __half* __restrict__ Wf,
        const float* __restrict__ bias, void* outp, int mode) {
    extern __shared__ char smem[];
    u32 sb = smem_u32(smem);

    int tid = threadIdx.x;
    int lane = tid & 31;
    int wid = tid >> 5;
    int wm = wid & 3;
    int wn = wid >> 2;
    int bm = blockIdx.y * 128;
    int bn = blockIdx.x * 128;

    float acc[2][4][4];
#pragma unroll
    for (int i = 0; i < 2; i++)
#pragma unroll
        for (int j = 0; j < 4; j++)
#pragma unroll
            for (int r = 0; r < 4; r++) acc[i][j][r] = 0.f;

    auto load_chunk = [&](int c, int s) {
        u32 st = sb + s * STAGE_BYTES;
        int c0 = c * KCH;
#pragma unroll
        for (int u = tid; u < 1024; u += 512) {
            int row = u >> 3, seg = u & 7;
            size_t gofs = (size_t)(bm + row) * C_ + c0 + seg * 8;
            CP_ASYNC16(st + A_OFF + (u32)(row * SA + seg * 8) * 2, Af + gofs);
        }
#pragma unroll
        for (int u = tid; u < 1024; u += 512) {
            int row = u >> 4, seg = u & 15;
            size_t gofs = (size_t)(c0 + row) * C_ + bn + seg * 8;
            CP_ASYNC16(st + B_OFF + (u32)(row * SB + seg * 8) * 2, Wf + gofs);
        }
        CP_COMMIT();
    };

    load_chunk(0, 0);
    load_chunk(1, 1);

    int lr = lane & 15;
    int lh = lane >> 4;

    for (int c = 0; c < NCH; c++) {
        if (c + 2 < NCH) load_chunk(c + 2, (c + 2) & 3);
        if (c < NCH - 2)      CP_WAIT2();
        else if (c < NCH - 1) CP_WAIT1();
        else                  CP_WAIT0();
        __syncthreads();

        u32 st = sb + (c & 3) * STAGE_BYTES;
#pragma unroll
        for (int ks = 0; ks < 4; ks++) {
            int k0 = ks * 16;
            u32 af[2][4];
#pragma unroll
            for (int mt = 0; mt < 2; mt++) {
                u32 arow = (u32)(wm * 32 + mt * 16 + lr);
                u32 aoff = (arow * SA + k0 + lh * 8) * 2;
                ldsm_x4(st + A_OFF + aoff, af[mt][0], af[mt][1], af[mt][2], af[mt][3]);
            }
#pragma unroll
            for (int np = 0; np < 2; np++) {
                u32 brow = (u32)(k0 + lr);
                u32 bcol = (u32)(wn * 32 + np * 16 + lh * 8);
                u32 boff = (brow * SB + bcol) * 2;
                u32 b0, b1, b2, b3;
                ldsm_x4_t(st + B_OFF + boff, b0, b1, b2, b3);
#pragma unroll
                for (int mt = 0; mt < 2; mt++) {
                    mma_f16(acc[mt][np * 2],     af[mt][0], af[mt][1], af[mt][2], af[mt][3], b0, b1);
                    mma_f16(acc[mt][np * 2 + 1], af[mt][0], af[mt][1], af[mt][2], af[mt][3], b2, b3);
                }
            }
        }
    }
    __syncthreads();

    int rq = lane >> 2;
    int cq = (lane & 3) * 2;

    if (mode == 0) {
        float* out = (float*)outp;
#pragma unroll
        for (int mt = 0; mt < 2; mt++)
#pragma unroll
            for (int nt = 0; nt < 4; nt++) {
                int gc = bn + wn * 32 + nt * 8 + cq;
                float b0 = bias[gc], b1 = bias[gc + 1];
#pragma unroll
                for (int half = 0; half < 2; half++) {
                    int grow = bm + wm * 32 + mt * 16 + rq + half * 8;
                    float2 o;
                    o.x = acc[mt][nt][half * 2 + 0] + b0;
                    o.y = acc[mt][nt][half * 2 + 1] + b1;
                    *(float2*)(out + (size_t)grow * C_ + gc) = o;
                }
            }
    } else if (mode == 3) {
        __half* out = (__half*)outp;
#pragma unroll
        for (int mt = 0; mt < 2; mt++)
#pragma unroll
            for (int nt = 0; nt < 4; nt++) {
                int gc = bn + wn * 32 + nt * 8 + cq;
                float b0 = bias[gc], b1 = bias[gc + 1];
                int h = gc >> 6, d0 = gc & 63;
#pragma unroll
                for (int half = 0; half < 2; half++) {
                    int grow = bm + wm * 32 + mt * 16 + rq + half * 8;
                    int b = grow >> 11, t = grow & (T_ - 1);
                    __half2 o = __floats2half2_rn(acc[mt][nt][half * 2 + 0] + b0,
                                                  acc[mt][nt][half * 2 + 1] + b1);
                    *(__half2*)(out + (((size_t)b * H_ + h) * T_ + t) * D_ + d0) = o;
                }
            }
    } else {
        // Q/K: stage fp32 tile in smem, rope pairs (d, d+32) -> fp16, x2 vectorized
        float* cs = (float*)smem;
#pragma unroll
        for (int mt = 0; mt < 2; mt++)
#pragma unroll
            for (int nt = 0; nt < 4; nt++) {
                int lc = wn * 32 + nt * 8 + cq;
                int gc = bn + lc;
                float b0 = bias[gc], b1 = bias[gc + 1];
#pragma unroll
                for (int half = 0; half < 2; half++) {
                    int lrow = wm * 32 + mt * 16 + rq + half * 8;
                    cs[lrow * 132 + lc]     = acc[mt][nt][half * 2 + 0] + b0;
                    cs[lrow * 132 + lc + 1] = acc[mt][nt][half * 2 + 1] + b1;
                }
            }
        __syncthreads();

        __half* out = (__half*)outp;
        // Q carries the softmax scale in log2 domain: 1/8 * log2(e)
        float qscale = (mode == 1) ? 0.125f * LOG2E : 1.0f;
#pragma unroll
        for (int u = tid; u < 4096; u += 512) {
            int r  = u >> 5;                 // row 0..127
            int pp = u & 31;
            int hh = pp >> 4;                // which 64-col head half
            int dd = (pp & 15) * 2;          // 0..30 even
            int c  = hh * 64 + dd;
            int gc = bn + c;
            int h = gc >> 6;
            int grow = bm + r;
            int b = grow >> 11, t = grow & (T_ - 1);
            float x1a = cs[r * 132 + c],      x1b = cs[r * 132 + c + 1];
            float x2a = cs[r * 132 + c + 32], x2b = cs[r * 132 + c + 33];
            float2 cv = *(const float2*)&g_cos[(t << 6) + dd];
            float2 sv = *(const float2*)&g_sin[(t << 6) + dd];
            __half2 ya = __floats2half2_rn((x1a * cv.x - x2a * sv.x) * qscale,
                                           (x1b * cv.y - x2b * sv.y) * qscale);
            __half2 yb = __floats2half2_rn((x2a * cv.x + x1a * sv.x) * qscale,
                                           (x2b * cv.y + x1b * sv.y) * qscale);
            __half* dp = out + (((size_t)b * H_ + h) * T_ + t) * D_ + dd;
            *(__half2*)dp        = ya;
            *(__half2*)(dp + 32) = yb;
        }
    }
}

__global__ __launch_bounds__(512, 1) void mma_qkv_kernel(
        const float* __restrict__ bq, const float* __restrict__ bk,
        const float* __restrict__ bv) {
    int z = blockIdx.z;
    const __half* Wf = g_w + (size_t)z * C_ * C_;
    const float* bias = z == 0 ? bq : z == 1 ? bk : bv;
    void* dst = z == 0 ? (void*)g_qf : z == 1 ? (void*)g_kf : (void*)g_vf;
    hmma_gemm_body(g_xf, Wf, bias, dst, z + 1);
}

__global__ __launch_bounds__(512, 1) void mma_proj_kernel(
        const float* __restrict__ bp, float* __restrict__ out) {
    hmma_gemm_body(g_yf, g_w + 3 * (size_t)C_ * C_, bp, out, 0);
}

// ---------------------------------------------------------------------------
// HMMA flash attention v7: R11 structure (unconditional loops) + log2-domain
// softmax with ex2.approx.f16x2. 64 q / CTA (4 warps), 4-stage KV pipeline.
// ---------------------------------------------------------------------------
#define AST 72
#define KV_ARRB (64 * AST * 2)               // 9216
#define KV_STAGEB (2 * KV_ARRB)              // 18432 (K, V)
#define AT_SMEM (4 * KV_STAGEB + T_ * 4)     // 81920

__global__ __launch_bounds__(128) void attn_mma_kernel() {
    extern __shared__ char asm_[];
    u32 sbase = smem_u32(asm_);
    float* sbias = (float*)(asm_ + 4 * KV_STAGEB);
    __half* sst = (__half*)asm_;

    int bh = blockIdx.y;
    int h = bh & (H_ - 1);
    int qb = gridDim.x - 1 - blockIdx.x;      // big-work CTAs first
    int q0 = qb * 64;
    int tid = threadIdx.x;
    int lane = tid & 31;
    int w = tid >> 5;                         // 0..3
    int qw = q0 + w * 16;

    const __half* qf = g_qf + ((size_t)bh * T_ + q0) * D_;
    size_t kvo = (size_t)bh * T_ * D_;

    {
        const float4* b4 = (const float4*)(g_bias + h * T_);
        const float bs = 0.125f * LOG2E;
        for (int i = tid; i < T_ / 4; i += 128) {
            float4 v = b4[i];
            v.x *= bs; v.y *= bs; v.z *= bs; v.w *= bs;
            ((float4*)sbias)[i] = v;
        }
    }
    // stage Q (64x64 fp16) into stage-0 area
    for (int u = tid; u < 512; u += 128) {
        int row = u >> 3, seg = u & 7;
        *(uint4*)(sst + row * AST + seg * 8) =
            *(const uint4*)(qf + row * 64 + seg * 8);
    }
    __syncthreads();

    u32 qfr[4][4];
    {
        int lr = lane & 15, lh = lane >> 4;
#pragma unroll
        for (int kc = 0; kc < 4; kc++) {
            u32 off = (u32)((w * 16 + lr) * AST + kc * 16 + lh * 8) * 2;
            ldsm_x4(sbase + off, qfr[kc][0], qfr[kc][1], qfr[kc][2], qfr[kc][3]);
        }
    }
    __syncthreads();

    auto load_kv = [&](int blk, int s) {
        u32 st = sbase + s * KV_STAGEB;
        const __half* kf = g_kf + kvo + (size_t)blk * 64 * 64;
        const __half* vf = g_vf + kvo + (size_t)blk * 64 * 64;
#pragma unroll
        for (int u = tid; u < 512; u += 128) {
            int row = u >> 3, seg = u & 7;
            u32 doff = (u32)(row * AST + seg * 8) * 2;
            int goff = row * 64 + seg * 8;
            CP_ASYNC16(st + doff,           kf + goff);
            CP_ASYNC16(st + KV_ARRB + doff, vf + goff);
        }
        CP_COMMIT();
    };

    int nblk = qb + 1;
    load_kv(0, 0);
    if (nblk > 1) load_kv(1, 1);

    float mlo = -CUDART_INF_F, mhi = -CUDART_INF_F;
    float llo = 0.f, lhi = 0.f;
    float oacc[8][4];
#pragma unroll
    for (int i = 0; i < 8; i++)
#pragma unroll
        for (int j = 0; j < 4; j++) oacc[i][j] = 0.f;

    int rlo = qw + (lane >> 2);
    int rhi = rlo + 8;
    int cq = (lane & 3) * 2;

    for (int blk = 0; blk < nblk; blk++) {
        if (blk + 2 < nblk) load_kv(blk + 2, (blk + 2) & 3);
        if (blk < nblk - 2)      CP_WAIT2();
        else if (blk < nblk - 1) CP_WAIT1();
        else                     CP_WAIT0();
        __syncthreads();

        int j0 = blk * 64;
        {
            u32 st = sbase + (blk & 3) * KV_STAGEB;
            int lr = lane & 15, lh = lane >> 4;

            // S = Q K^T (log2 domain)
            float sacc[8][4];
#pragma unroll
            for (int i = 0; i < 8; i++)
#pragma unroll
                for (int j = 0; j < 4; j++) sacc[i][j] = 0.f;
#pragma unroll
            for (int kg = 0; kg < 4; kg++) {
#pragma unroll
                for (int kc = 0; kc < 4; kc++) {
                    u32 off = (u32)((kg * 16 + lr) * AST + kc * 16 + lh * 8) * 2;
                    u32 k0, k1, k2, k3;
                    ldsm_x4(st + off, k0, k1, k2, k3);
                    mma_f16(sacc[2 * kg],     qfr[kc][0], qfr[kc][1], qfr[kc][2], qfr[kc][3], k0, k2);
                    mma_f16(sacc[2 * kg + 1], qfr[kc][0], qfr[kc][1], qfr[kc][2], qfr[kc][3], k1, k3);
                }
            }

            // bias + causal mask
#pragma unroll
            for (int nf = 0; nf < 8; nf++) {
                int jc = j0 + nf * 8 + cq;
                int d0 = rlo - jc;
                int d2 = rhi - jc;
                sacc[nf][0] = (d0 >= 0) ? sacc[nf][0] + sbias[d0]     : -CUDART_INF_F;
                sacc[nf][1] = (d0 >= 1) ? sacc[nf][1] + sbias[d0 - 1] : -CUDART_INF_F;
                sacc[nf][2] = (d2 >= 0) ? sacc[nf][2] + sbias[d2]     : -CUDART_INF_F;
                sacc[nf][3] = (d2 >= 1) ? sacc[nf][3] + sbias[d2 - 1] : -CUDART_INF_F;
            }

            // row max
            float bmlo = sacc[0][0], bmhi = sacc[0][2];
#pragma unroll
            for (int nf = 0; nf < 8; nf++) {
                bmlo = fmaxf(bmlo, fmaxf(sacc[nf][0], sacc[nf][1]));
                bmhi = fmaxf(bmhi, fmaxf(sacc[nf][2], sacc[nf][3]));
            }
            bmlo = fmaxf(bmlo, __shfl_xor_sync(0xffffffffu, bmlo, 1));
            bmlo = fmaxf(bmlo, __shfl_xor_sync(0xffffffffu, bmlo, 2));
            bmhi = fmaxf(bmhi, __shfl_xor_sync(0xffffffffu, bmhi, 1));
            bmhi = fmaxf(bmhi, __shfl_xor_sync(0xffffffffu, bmhi, 2));

            float nmlo = fmaxf(mlo, bmlo), nmhi = fmaxf(mhi, bmhi);
            float clo = ex2_f32(mlo - nmlo), chi = ex2_f32(mhi - nmhi);
            mlo = nmlo; mhi = nmhi;
            llo *= clo; lhi *= chi;
#pragma unroll
            for (int nf = 0; nf < 8; nf++) {
                oacc[nf][0] *= clo; oacc[nf][1] *= clo;
                oacc[nf][2] *= chi; oacc[nf][3] *= chi;
            }

            // P = 2^(s - m) via packed fp16 ex2 (one MUFU per 2 values)
            u32 pf[4][4];
#pragma unroll
            for (int nf = 0; nf < 8; nf++) {
                u32 p01 = ex2_f16x2(sacc[nf][0] - mlo, sacc[nf][1] - mlo);
                u32 p23 = ex2_f16x2(sacc[nf][2] - mhi, sacc[nf][3] - mhi);
                float2 f01 = __half22float2(*(__half2*)&p01);
                float2 f23 = __half22float2(*(__half2*)&p23);
                llo += f01.x + f01.y;
                lhi += f23.x + f23.y;
                int kc = nf >> 1, half = nf & 1;
                pf[kc][half * 2 + 0] = p01;
                pf[kc][half * 2 + 1] = p23;
            }

            // O += P V
#pragma unroll
            for (int dg = 0; dg < 4; dg++) {
#pragma unroll
                for (int kc = 0; kc < 4; kc++) {
                    u32 off = (u32)((kc * 16 + lr) * AST + dg * 16 + lh * 8) * 2;
                    u32 v0, v1, v2, v3;
                    ldsm_x4_t(st + KV_ARRB + off, v0, v1, v2, v3);
                    mma_f16(oacc[2 * dg],     pf[kc][0], pf[kc][1], pf[kc][2], pf[kc][3], v0, v1);
                    mma_f16(oacc[2 * dg + 1], pf[kc][0], pf[kc][1], pf[kc][2], pf[kc][3], v2, v3);
                }
            }
        }
    }

    llo += __shfl_xor_sync(0xffffffffu, llo, 1);
    llo += __shfl_xor_sync(0xffffffffu, llo, 2);
    lhi += __shfl_xor_sync(0xffffffffu, lhi, 1);
    lhi += __shfl_xor_sync(0xffffffffu, lhi, 2);
    float ilo = 1.f / llo, ihi = 1.f / lhi;

    // write fp16 directly to proj input g_yf [B*T, C]
    int b = bh >> 4;
    __half* ylo = g_yf + ((size_t)b * T_ + rlo) * C_ + h * D_ + cq;
    __half* yhi = g_yf + ((size_t)b * T_ + rhi) * C_ + h * D_ + cq;
#pragma unroll
    for (int nf = 0; nf < 8; nf++) {
        *(__half2*)(ylo + nf * 8) = __floats2half2_rn(oacc[nf][0] * ilo, oacc[nf][1] * ilo);
        *(__half2*)(yhi + nf * 8) = __floats2half2_rn(oacc[nf][2] * ihi, oacc[nf][3] * ihi);
    }
}

// ---------------------------------------------------------------------------
extern "C" void kernel_launch(void* const* d_in, const int* in_sizes, int n_in,
                              void* d_out, int out_size) {
    const float* x   = (const float*)d_in[0];
    const float* Wq  = (const float*)d_in[1];
    const float* bq  = (const float*)d_in[2];
    const float* Wk  = (const float*)d_in[3];
    const float* bk  = (const float*)d_in[4];
    const float* Wv  = (const float*)d_in[5];
    const float* bv  = (const float*)d_in[6];
    const float* Wp  = (const float*)d_in[7];
    const float* bp  = (const float*)d_in[8];
    const float* tbl = (const float*)d_in[9];
    float* out = (float*)d_out;

    cudaFuncSetAttribute(mma_qkv_kernel,
                         cudaFuncAttributeMaxDynamicSharedMemorySize, SMEM_TOTAL);
    cudaFuncSetAttribute(mma_proj_kernel,
                         cudaFuncAttributeMaxDynamicSharedMemorySize, SMEM_TOTAL);
    cudaFuncSetAttribute(attn_mma_kernel,
                         cudaFuncAttributeMaxDynamicSharedMemorySize, AT_SMEM);

    prep_kernel<<<8704, 256>>>(x, Wq, Wk, Wv, Wp, tbl);

    mma_qkv_kernel<<<dim3(C_ / 128, (B_ * T_) / 128, 3), 512, SMEM_TOTAL>>>(bq, bk, bv);

    attn_mma_kernel<<<dim3(T_ / 64, B_ * H_), 128, AT_SMEM>>>();

    mma_proj_kernel<<<dim3(C_ / 128, (B_ * T_) / 128), 512, SMEM_TOTAL>>>(bp, out);
}

// round 14
// speedup vs baseline: 1.3024x; 1.0975x over previous
#include <cuda_runtime.h>
#include <cuda_fp16.h>
#include <math.h>
#include <math_constants.h>

#define B_  2
#define T_  2048
#define C_  1024
#define H_  16
#define D_  64
#define KCH 64               // GEMM K elems per pipeline chunk
#define NCH (C_ / KCH)       // 16 chunks

#define LOG2E 1.44269504f

typedef unsigned int u32;

// ---------------------------------------------------------------------------
// Scratch (__device__ globals: allocation-free rule)
// ---------------------------------------------------------------------------
static __device__ __align__(16) float g_bias[H_*T_];
static __device__ __align__(16) float g_cos[T_*D_];
static __device__ __align__(16) float g_sin[T_*D_];
// fp16 operands
static __device__ __align__(16) __half g_xf[(size_t)B_*T_*C_];      // x fp16
static __device__ __align__(16) __half g_yf[(size_t)B_*T_*C_];      // attn out fp16
static __device__ __align__(16) __half g_w[4 * (size_t)C_*C_];      // weights fp16
// attention operands (head layout [B,H,T,D]), written by fused qkv epilogue
static __device__ __align__(16) __half g_qf[(size_t)B_*H_*T_*D_];   // pre-scaled by 0.125*log2e
static __device__ __align__(16) __half g_kf[(size_t)B_*H_*T_*D_];
static __device__ __align__(16) __half g_vf[(size_t)B_*H_*T_*D_];

// ---------------------------------------------------------------------------
// Baseline-PTX helpers (sm_80-compatible: ldmatrix / mma.sync / cp.async)
// ---------------------------------------------------------------------------
__device__ __forceinline__ u32 smem_u32(const void* p) {
    u32 a;
    asm("{ .reg .u64 t; cvta.to.shared.u64 t, %1; cvt.u32.u64 %0, t; }" : "=r"(a) : "l"(p));
    return a;
}
__device__ __forceinline__ void ldsm_x4(u32 addr, u32& r0, u32& r1, u32& r2, u32& r3) {
    asm volatile("ldmatrix.sync.aligned.m8n8.x4.shared.b16 {%0,%1,%2,%3}, [%4];"
                 : "=r"(r0), "=r"(r1), "=r"(r2), "=r"(r3) : "r"(addr));
}
__device__ __forceinline__ void ldsm_x4_t(u32 addr, u32& r0, u32& r1, u32& r2, u32& r3) {
    asm volatile("ldmatrix.sync.aligned.m8n8.x4.trans.shared.b16 {%0,%1,%2,%3}, [%4];"
                 : "=r"(r0), "=r"(r1), "=r"(r2), "=r"(r3) : "r"(addr));
}
__device__ __forceinline__ void mma_f16(float* c, u32 a0, u32 a1, u32 a2, u32 a3,
                                        u32 b0, u32 b1) {
    asm volatile("mma.sync.aligned.m16n8k16.row.col.f32.f16.f16.f32 "
                 "{%0,%1,%2,%3}, {%4,%5,%6,%7}, {%8,%9}, {%0,%1,%2,%3};"
                 : "+f"(c[0]), "+f"(c[1]), "+f"(c[2]), "+f"(c[3])
                 : "r"(a0), "r"(a1), "r"(a2), "r"(a3), "r"(b0), "r"(b1));
}
#define CP_ASYNC16(dst, src) \
    asm volatile("cp.async.cg.shared.global [%0], [%1], 16;" :: "r"(dst), "l"(src))
#define CP_COMMIT() asm volatile("cp.async.commit_group;" ::: "memory")
#define CP_WAIT2()  asm volatile("cp.async.wait_group 2;" ::: "memory")
#define CP_WAIT1()  asm volatile("cp.async.wait_group 1;" ::: "memory")
#define CP_WAIT0()  asm volatile("cp.async.wait_group 0;" ::: "memory")

// packed fp16x2 2^x (one MUFU for two values)
__device__ __forceinline__ u32 ex2_f16x2(float a, float b) {
    __half2 h = __floats2half2_rn(a, b);
    u32 r;
    asm("ex2.approx.f16x2 %0, %1;" : "=r"(r) : "r"(*(u32*)&h));
    return r;
}
__device__ __forceinline__ float ex2_f32(float a) {
    float r;
    asm("ex2.approx.f32 %0, %1;" : "=f"(r) : "f"(a));
    return r;
}

// ---------------------------------------------------------------------------
// Fused prep: convert x, convert W, build tables (one launch)
// ---------------------------------------------------------------------------
__global__ void prep_kernel(const float* __restrict__ xin,
                            const float* __restrict__ Wq, const float* __restrict__ Wk,
                            const float* __restrict__ Wv, const float* __restrict__ Wp,
                            const float* __restrict__ rel_table) {
    int bx = blockIdx.x;
    int tid = threadIdx.x;
    if (bx < 4096) {
        int i = bx * 256 + tid;
        float4 v = ((const float4*)xin)[i];
        ((__half2*)g_xf)[i * 2 + 0] = __floats2half2_rn(v.x, v.y);
        ((__half2*)g_xf)[i * 2 + 1] = __floats2half2_rn(v.z, v.w);
    } else if (bx < 8192) {
        int bx2 = bx - 4096;
        int z = bx2 >> 10;
        const float* W = z == 0 ? Wq : z == 1 ? Wk : z == 2 ? Wv : Wp;
        __half* ow = g_w + (size_t)z * C_ * C_;
        int i = (bx2 & 1023) * 256 + tid;
        float4 v = ((const float4*)W)[i];
        ((__half2*)ow)[i * 2 + 0] = __floats2half2_rn(v.x, v.y);
        ((__half2*)ow)[i * 2 + 1] = __floats2half2_rn(v.z, v.w);
    } else {
        int idx = (bx - 8192) * 256 + tid;
        if (idx < T_ * D_) {
            int t = idx >> 6;
            int d = idx & 63;
            int j = d & 31;
            float inv = (float)pow(10000.0, -(double)(2 * j) / 64.0);
            float fr = (float)t * inv;
            g_cos[idx] = cosf(fr);
            g_sin[idx] = sinf(fr);
        }
        if (idx < H_ * T_) {
            int h = idx / T_;
            int n = idx % T_;
            int bucket;
            if (n < 16) {
                bucket = n;
            } else {
                float v = logf((float)n * (1.0f / 16.0f)) / 2.0794415416798357f * 16.0f;
                bucket = 16 + (int)v;
                if (bucket > 31) bucket = 31;
            }
            g_bias[idx] = rel_table[bucket * H_ + h];
        }
    }
}

// ---------------------------------------------------------------------------
// HMMA GEMM v8: 256 threads, 8 warps (2x4), warp tile 64x32 (R4 geometry),
// 2-stage cp.async pipeline, 2 CTAs/SM. A fp16 x W fp16 (1 product).
// mode 0: proj (fp32 out)  1: Q (rope+log2e scale)  2: K (rope)  3: V (fp16)
// ---------------------------------------------------------------------------
#define SA 72        // A smem row stride (halves)
#define SB 136       // B smem row stride (halves)
#define A_OFF 0
#define B_OFF (128 * SA * 2)                      // 18432
#define STAGE_BYTES (B_OFF + KCH * SB * 2)        // 35840
#define SMEM_TOTAL (2 * STAGE_BYTES)              // 71680

__device__ __forceinline__ void hmma_gemm_body(
        const __half* __restrict__ Af, const __half* __restrict__ Wf,
        const float* __restrict__ bias, void* outp, int mode) {
    extern __shared__ char smem[];
    u32 sb = smem_u32(smem);

    int tid = threadIdx.x;
    int lane = tid & 31;
    int wid = tid >> 5;       // 0..7
    int wm = wid & 1;         // 2 row groups of 64
    int wn = wid >> 1;        // 4 col groups of 32
    int bm = blockIdx.y * 128;
    int bn = blockIdx.x * 128;

    float acc[4][4][4];
#pragma unroll
    for (int i = 0; i < 4; i++)
#pragma unroll
        for (int j = 0; j < 4; j++)
#pragma unroll
            for (int r = 0; r < 4; r++) acc[i][j][r] = 0.f;

    auto load_chunk = [&](int c, int s) {
        u32 st = sb + s * STAGE_BYTES;
        int c0 = c * KCH;
        // A: 128 rows x 64 halves = 1024 16B segs
#pragma unroll
        for (int u = tid; u < 1024; u += 256) {
            int row = u >> 3, seg = u & 7;
            size_t gofs = (size_t)(bm + row) * C_ + c0 + seg * 8;
            CP_ASYNC16(st + A_OFF + (u32)(row * SA + seg * 8) * 2, Af + gofs);
        }
        // B: 64 k-rows x 128 halves = 1024 16B segs
#pragma unroll
        for (int u = tid; u < 1024; u += 256) {
            int row = u >> 4, seg = u & 15;
            size_t gofs = (size_t)(c0 + row) * C_ + bn + seg * 8;
            CP_ASYNC16(st + B_OFF + (u32)(row * SB + seg * 8) * 2, Wf + gofs);
        }
        CP_COMMIT();
    };

    load_chunk(0, 0);

    int lr = lane & 15;
    int lh = lane >> 4;

    for (int c = 0; c < NCH; c++) {
        int s = c & 1;
        if (c + 1 < NCH) { load_chunk(c + 1, s ^ 1); CP_WAIT1(); }
        else             { CP_WAIT0(); }
        __syncthreads();

        u32 st = sb + s * STAGE_BYTES;
#pragma unroll
        for (int ks = 0; ks < 4; ks++) {
            int k0 = ks * 16;
            u32 af[4][4];
#pragma unroll
            for (int mt = 0; mt < 4; mt++) {
                u32 arow = (u32)(wm * 64 + mt * 16 + lr);
                u32 aoff = (arow * SA + k0 + lh * 8) * 2;
                ldsm_x4(st + A_OFF + aoff, af[mt][0], af[mt][1], af[mt][2], af[mt][3]);
            }
#pragma unroll
            for (int np = 0; np < 2; np++) {
                u32 brow = (u32)(k0 + lr);
                u32 bcol = (u32)(wn * 32 + np * 16 + lh * 8);
                u32 boff = (brow * SB + bcol) * 2;
                u32 b0, b1, b2, b3;
                ldsm_x4_t(st + B_OFF + boff, b0, b1, b2, b3);
#pragma unroll
                for (int mt = 0; mt < 4; mt++) {
                    mma_f16(acc[mt][np * 2],     af[mt][0], af[mt][1], af[mt][2], af[mt][3], b0, b1);
                    mma_f16(acc[mt][np * 2 + 1], af[mt][0], af[mt][1], af[mt][2], af[mt][3], b2, b3);
                }
            }
        }
        __syncthreads();
    }

    int rq = lane >> 2;
    int cq = (lane & 3) * 2;

    if (mode == 0) {
        float* out = (float*)outp;
#pragma unroll
        for (int mt = 0; mt < 4; mt++)
#pragma unroll
            for (int nt = 0; nt < 4; nt++) {
                int gc = bn + wn * 32 + nt * 8 + cq;
                float b0 = bias[gc], b1 = bias[gc + 1];
#pragma unroll
                for (int half = 0; half < 2; half++) {
                    int grow = bm + wm * 64 + mt * 16 + rq + half * 8;
                    float2 o;
                    o.x = acc[mt][nt][half * 2 + 0] + b0;
                    o.y = acc[mt][nt][half * 2 + 1] + b1;
                    *(float2*)(out + (size_t)grow * C_ + gc) = o;
                }
            }
    } else if (mode == 3) {
        __half* out = (__half*)outp;
#pragma unroll
        for (int mt = 0; mt < 4; mt++)
#pragma unroll
            for (int nt = 0; nt < 4; nt++) {
                int gc = bn + wn * 32 + nt * 8 + cq;
                float b0 = bias[gc], b1 = bias[gc + 1];
                int h = gc >> 6, d0 = gc & 63;
#pragma unroll
                for (int half = 0; half < 2; half++) {
                    int grow = bm + wm * 64 + mt * 16 + rq + half * 8;
                    int b = grow >> 11, t = grow & (T_ - 1);
                    __half2 o = __floats2half2_rn(acc[mt][nt][half * 2 + 0] + b0,
                                                  acc[mt][nt][half * 2 + 1] + b1);
                    *(__half2*)(out + (((size_t)b * H_ + h) * T_ + t) * D_ + d0) = o;
                }
            }
    } else {
        // Q/K: stage fp32 tile in smem, rope pairs (d, d+32) -> fp16, x2 vectorized
        float* cs = (float*)smem;
#pragma unroll
        for (int mt = 0; mt < 4; mt++)
#pragma unroll
            for (int nt = 0; nt < 4; nt++) {
                int lc = wn * 32 + nt * 8 + cq;
                int gc = bn + lc;
                float b0 = bias[gc], b1 = bias[gc + 1];
#pragma unroll
                for (int half = 0; half < 2; half++) {
                    int lrow = wm * 64 + mt * 16 + rq + half * 8;
                    cs[lrow * 132 + lc]     = acc[mt][nt][half * 2 + 0] + b0;
                    cs[lrow * 132 + lc + 1] = acc[mt][nt][half * 2 + 1] + b1;
                }
            }
        __syncthreads();

        __half* out = (__half*)outp;
        // Q carries the softmax scale in log2 domain: 1/8 * log2(e)
        float qscale = (mode == 1) ? 0.125f * LOG2E : 1.0f;
#pragma unroll
        for (int u = tid; u < 4096; u += 256) {
            int r  = u >> 5;                 // row 0..127
            int pp = u & 31;
            int hh = pp >> 4;                // which 64-col head half
            int dd = (pp & 15) * 2;          // 0..30 even
            int c  = hh * 64 + dd;
            int gc = bn + c;
            int h = gc >> 6;
            int grow = bm + r;
            int b = grow >> 11, t = grow & (T_ - 1);
            float x1a = cs[r * 132 + c],      x1b = cs[r * 132 + c + 1];
            float x2a = cs[r * 132 + c + 32], x2b = cs[r * 132 + c + 33];
            float2 cv = *(const float2*)&g_cos[(t << 6) + dd];
            float2 sv = *(const float2*)&g_sin[(t << 6) + dd];
            __half2 ya = __floats2half2_rn((x1a * cv.x - x2a * sv.x) * qscale,
                                           (x1b * cv.y - x2b * sv.y) * qscale);
            __half2 yb = __floats2half2_rn((x2a * cv.x + x1a * sv.x) * qscale,
                                           (x2b * cv.y + x1b * sv.y) * qscale);
            __half* dp = out + (((size_t)b * H_ + h) * T_ + t) * D_ + dd;
            *(__half2*)dp        = ya;
            *(__half2*)(dp + 32) = yb;
        }
    }
}

__global__ __launch_bounds__(256, 2) void mma_qkv_kernel(
        const float* __restrict__ bq, const float* __restrict__ bk,
        const float* __restrict__ bv) {
    int z = blockIdx.z;
    const __half* Wf = g_w + (size_t)z * C_ * C_;
    const float* bias = z == 0 ? bq : z == 1 ? bk : bv;
    void* dst = z == 0 ? (void*)g_qf : z == 1 ? (void*)g_kf : (void*)g_vf;
    hmma_gemm_body(g_xf, Wf, bias, dst, z + 1);
}

__global__ __launch_bounds__(256, 2) void mma_proj_kernel(
        const float* __restrict__ bp, float* __restrict__ out) {
    hmma_gemm_body(g_yf, g_w + 3 * (size_t)C_ * C_, bp, out, 0);
}

// ---------------------------------------------------------------------------
// HMMA flash attention (unchanged R13): 64 q / CTA (4 warps), 4-stage KV
// pipeline, log2-domain softmax with ex2.approx.f16x2.
// ---------------------------------------------------------------------------
#define AST 72
#define KV_ARRB (64 * AST * 2)               // 9216
#define KV_STAGEB (2 * KV_ARRB)              // 18432 (K, V)
#define AT_SMEM (4 * KV_STAGEB + T_ * 4)     // 81920

__global__ __launch_bounds__(128) void attn_mma_kernel() {
    extern __shared__ char asm_[];
    u32 sbase = smem_u32(asm_);
    float* sbias = (float*)(asm_ + 4 * KV_STAGEB);
    __half* sst = (__half*)asm_;

    int bh = blockIdx.y;
    int h = bh & (H_ - 1);
    int qb = gridDim.x - 1 - blockIdx.x;      // big-work CTAs first
    int q0 = qb * 64;
    int tid = threadIdx.x;
    int lane = tid & 31;
    int w = tid >> 5;                         // 0..3
    int qw = q0 + w * 16;

    const __half* qf = g_qf + ((size_t)bh * T_ + q0) * D_;
    size_t kvo = (size_t)bh * T_ * D_;

    {
        const float4* b4 = (const float4*)(g_bias + h * T_);
        const float bs = 0.125f * LOG2E;
        for (int i = tid; i < T_ / 4; i += 128) {
            float4 v = b4[i];
            v.x *= bs; v.y *= bs; v.z *= bs; v.w *= bs;
            ((float4*)sbias)[i] = v;
        }
    }
    // stage Q (64x64 fp16) into stage-0 area
    for (int u = tid; u < 512; u += 128) {
        int row = u >> 3, seg = u & 7;
        *(uint4*)(sst + row * AST + seg * 8) =
            *(const uint4*)(qf + row * 64 + seg * 8);
    }
    __syncthreads();

    u32 qfr[4][4];
    {
        int lr = lane & 15, lh = lane >> 4;
#pragma unroll
        for (int kc = 0; kc < 4; kc++) {
            u32 off = (u32)((w * 16 + lr) * AST + kc * 16 + lh * 8) * 2;
            ldsm_x4(sbase + off, qfr[kc][0], qfr[kc][1], qfr[kc][2], qfr[kc][3]);
        }
    }
    __syncthreads();

    auto load_kv = [&](int blk, int s) {
        u32 st = sbase + s * KV_STAGEB;
        const __half* kf = g_kf + kvo + (size_t)blk * 64 * 64;
        const __half* vf = g_vf + kvo + (size_t)blk * 64 * 64;
#pragma unroll
        for (int u = tid; u < 512; u += 128) {
            int row = u >> 3, seg = u & 7;
            u32 doff = (u32)(row * AST + seg * 8) * 2;
            int goff = row * 64 + seg * 8;
            CP_ASYNC16(st + doff,           kf + goff);
            CP_ASYNC16(st + KV_ARRB + doff, vf + goff);
        }
        CP_COMMIT();
    };

    int nblk = qb + 1;
    load_kv(0, 0);
    if (nblk > 1) load_kv(1, 1);

    float mlo = -CUDART_INF_F, mhi = -CUDART_INF_F;
    float llo = 0.f, lhi = 0.f;
    float oacc[8][4];
#pragma unroll
    for (int i = 0; i < 8; i++)
#pragma unroll
        for (int j = 0; j < 4; j++) oacc[i][j] = 0.f;

    int rlo = qw + (lane >> 2);
    int rhi = rlo + 8;
    int cq = (lane & 3) * 2;

    for (int blk = 0; blk < nblk; blk++) {
        if (blk + 2 < nblk) load_kv(blk + 2, (blk + 2) & 3);
        if (blk < nblk - 2)      CP_WAIT2();
        else if (blk < nblk - 1) CP_WAIT1();
        else                     CP_WAIT0();
        __syncthreads();

        int j0 = blk * 64;
        {
            u32 st = sbase + (blk & 3) * KV_STAGEB;
            int lr = lane & 15, lh = lane >> 4;

            // S = Q K^T (log2 domain)
            float sacc[8][4];
#pragma unroll
            for (int i = 0; i < 8; i++)
#pragma unroll
                for (int j = 0; j < 4; j++) sacc[i][j] = 0.f;
#pragma unroll
            for (int kg = 0; kg < 4; kg++) {
#pragma unroll
                for (int kc = 0; kc < 4; kc++) {
                    u32 off = (u32)((kg * 16 + lr) * AST + kc * 16 + lh * 8) * 2;
                    u32 k0, k1, k2, k3;
                    ldsm_x4(st + off, k0, k1, k2, k3);
                    mma_f16(sacc[2 * kg],     qfr[kc][0], qfr[kc][1], qfr[kc][2], qfr[kc][3], k0, k2);
                    mma_f16(sacc[2 * kg + 1], qfr[kc][0], qfr[kc][1], qfr[kc][2], qfr[kc][3], k1, k3);
                }
            }

            // bias + causal mask
#pragma unroll
            for (int nf = 0; nf < 8; nf++) {
                int jc = j0 + nf * 8 + cq;
                int d0 = rlo - jc;
                int d2 = rhi - jc;
                sacc[nf][0] = (d0 >= 0) ? sacc[nf][0] + sbias[d0]     : -CUDART_INF_F;
                sacc[nf][1] = (d0 >= 1) ? sacc[nf][1] + sbias[d0 - 1] : -CUDART_INF_F;
                sacc[nf][2] = (d2 >= 0) ? sacc[nf][2] + sbias[d2]     : -CUDART_INF_F;
                sacc[nf][3] = (d2 >= 1) ? sacc[nf][3] + sbias[d2 - 1] : -CUDART_INF_F;
            }

            // row max
            float bmlo = sacc[0][0], bmhi = sacc[0][2];
#pragma unroll
            for (int nf = 0; nf < 8; nf++) {
                bmlo = fmaxf(bmlo, fmaxf(sacc[nf][0], sacc[nf][1]));
                bmhi = fmaxf(bmhi, fmaxf(sacc[nf][2], sacc[nf][3]));
            }
            bmlo = fmaxf(bmlo, __shfl_xor_sync(0xffffffffu, bmlo, 1));
            bmlo = fmaxf(bmlo, __shfl_xor_sync(0xffffffffu, bmlo, 2));
            bmhi = fmaxf(bmhi, __shfl_xor_sync(0xffffffffu, bmhi, 1));
            bmhi = fmaxf(bmhi, __shfl_xor_sync(0xffffffffu, bmhi, 2));

            float nmlo = fmaxf(mlo, bmlo), nmhi = fmaxf(mhi, bmhi);
            float clo = ex2_f32(mlo - nmlo), chi = ex2_f32(mhi - nmhi);
            mlo = nmlo; mhi = nmhi;
            llo *= clo; lhi *= chi;
#pragma unroll
            for (int nf = 0; nf < 8; nf++) {
                oacc[nf][0] *= clo; oacc[nf][1] *= clo;
                oacc[nf][2] *= chi; oacc[nf][3] *= chi;
            }

            // P = 2^(s - m) via packed fp16 ex2 (one MUFU per 2 values)
            u32 pf[4][4];
#pragma unroll
            for (int nf = 0; nf < 8; nf++) {
                u32 p01 = ex2_f16x2(sacc[nf][0] - mlo, sacc[nf][1] - mlo);
                u32 p23 = ex2_f16x2(sacc[nf][2] - mhi, sacc[nf][3] - mhi);
                float2 f01 = __half22float2(*(__half2*)&p01);
                float2 f23 = __half22float2(*(__half2*)&p23);
                llo += f01.x + f01.y;
                lhi += f23.x + f23.y;
                int kc = nf >> 1, half = nf & 1;
                pf[kc][half * 2 + 0] = p01;
                pf[kc][half * 2 + 1] = p23;
            }

            // O += P V
#pragma unroll
            for (int dg = 0; dg < 4; dg++) {
#pragma unroll
                for (int kc = 0; kc < 4; kc++) {
                    u32 off = (u32)((kc * 16 + lr) * AST + dg * 16 + lh * 8) * 2;
                    u32 v0, v1, v2, v3;
                    ldsm_x4_t(st + KV_ARRB + off, v0, v1, v2, v3);
                    mma_f16(oacc[2 * dg],     pf[kc][0], pf[kc][1], pf[kc][2], pf[kc][3], v0, v1);
                    mma_f16(oacc[2 * dg + 1], pf[kc][0], pf[kc][1], pf[kc][2], pf[kc][3], v2, v3);
                }
            }
        }
    }

    llo += __shfl_xor_sync(0xffffffffu, llo, 1);
    llo += __shfl_xor_sync(0xffffffffu, llo, 2);
    lhi += __shfl_xor_sync(0xffffffffu, lhi, 1);
    lhi += __shfl_xor_sync(0xffffffffu, lhi, 2);
    float ilo = 1.f / llo, ihi = 1.f / lhi;

    // write fp16 directly to proj input g_yf [B*T, C]
    int b = bh >> 4;
    __half* ylo = g_yf + ((size_t)b * T_ + rlo) * C_ + h * D_ + cq;
    __half* yhi = g_yf + ((size_t)b * T_ + rhi) * C_ + h * D_ + cq;
#pragma unroll
    for (int nf = 0; nf < 8; nf++) {
        *(__half2*)(ylo + nf * 8) = __floats2half2_rn(oacc[nf][0] * ilo, oacc[nf][1] * ilo);
        *(__half2*)(yhi + nf * 8) = __floats2half2_rn(oacc[nf][2] * ihi, oacc[nf][3] * ihi);
    }
}

// ---------------------------------------------------------------------------
extern "C" void kernel_launch(void* const* d_in, const int* in_sizes, int n_in,
                              void* d_out, int out_size) {
    const float* x   = (const float*)d_in[0];
    const float* Wq  = (const float*)d_in[1];
    const float* bq  = (const float*)d_in[2];
    const float* Wk  = (const float*)d_in[3];
    const float* bk  = (const float*)d_in[4];
    const float* Wv  = (const float*)d_in[5];
    const float* bv  = (const float*)d_in[6];
    const float* Wp  = (const float*)d_in[7];
    const float* bp  = (const float*)d_in[8];
    const float* tbl = (const float*)d_in[9];
    float* out = (float*)d_out;

    cudaFuncSetAttribute(mma_qkv_kernel,
                         cudaFuncAttributeMaxDynamicSharedMemorySize, SMEM_TOTAL);
    cudaFuncSetAttribute(mma_proj_kernel,
                         cudaFuncAttributeMaxDynamicSharedMemorySize, SMEM_TOTAL);
    cudaFuncSetAttribute(attn_mma_kernel,
                         cudaFuncAttributeMaxDynamicSharedMemorySize, AT_SMEM);

    prep_kernel<<<8704, 256>>>(x, Wq, Wk, Wv, Wp, tbl);

    mma_qkv_kernel<<<dim3(C_ / 128, (B_ * T_) / 128, 3), 256, SMEM_TOTAL>>>(bq, bk, bv);

    attn_mma_kernel<<<dim3(T_ / 64, B_ * H_), 128, AT_SMEM>>>();

    mma_proj_kernel<<<dim3(C_ / 128, (B_ * T_) / 128), 256, SMEM_TOTAL>>>(bp, out);
}